// round 17
// baseline (speedup 1.0000x reference)
#include <cuda_runtime.h>
#include <cuda_bf16.h>
#include <math.h>
#include <cstdint>

// Problem dims
#define BB 512
#define TN 300
#define DD 200
#define HH 128
#define GG 512   // 4*H
#define MM (TN*BB)      // 153600 rows
#define KP 256          // padded K per segment

// ---------------- static device scratch ----------------
__device__ float g_xpA[(size_t)TN * BB * GG];
__device__ float g_xpB[(size_t)TN * BB * GG];
__device__ float g_f1 [(size_t)TN * BB * HH];
__device__ float g_r1 [(size_t)TN * BB * HH];
__device__ float4 g_whhT4[4 * HH * HH];          // [mat][k][h] -> (g0,g1,g2,g3)
__device__ float g_wl1T[456 * HH];
__device__ float g_pooled[BB * HH];
__device__ __nv_bfloat16 g_Ahi[(size_t)MM * KP];
__device__ __nv_bfloat16 g_Alo[(size_t)MM * KP];
__device__ __nv_bfloat16 g_W[4 * 2 * GG * KP];   // [proj][hi/lo][512][256]

__device__ __forceinline__ void atomicMaxF(float* addr, float v) {
    if (v >= 0.f) atomicMax((int*)addr, __float_as_int(v));
    else          atomicMin((unsigned int*)addr, __float_as_uint(v));
}

// ================= PTX helpers =================
__device__ __forceinline__ uint32_t smem_u32(const void* p) {
    uint32_t addr;
    asm("{ .reg .u64 tmp; cvta.to.shared.u64 tmp, %1; cvt.u32.u64 %0, tmp; }"
        : "=r"(addr) : "l"(p));
    return addr;
}
#define CP_ASYNC16(dst, src) \
    asm volatile("cp.async.ca.shared.global [%0], [%1], 16;" :: "r"(dst), "l"(src))
#define CP_COMMIT() asm volatile("cp.async.commit_group;" ::: "memory")
#define CP_WAIT1()  asm volatile("cp.async.wait_group 1;" ::: "memory")
#define CP_WAIT0()  asm volatile("cp.async.wait_group 0;" ::: "memory")

__device__ __forceinline__ void ldsm_x4(uint32_t& r0, uint32_t& r1, uint32_t& r2, uint32_t& r3,
                                        uint32_t addr) {
    asm volatile("ldmatrix.sync.aligned.m8n8.x4.shared.b16 {%0,%1,%2,%3}, [%4];"
        : "=r"(r0), "=r"(r1), "=r"(r2), "=r"(r3) : "r"(addr));
}
__device__ __forceinline__ void mma16816(float* d, const uint32_t* a, uint32_t b0, uint32_t b1) {
    asm volatile(
        "mma.sync.aligned.m16n8k16.row.col.f32.bf16.bf16.f32 "
        "{%0,%1,%2,%3}, {%4,%5,%6,%7}, {%8,%9}, {%0,%1,%2,%3};"
        : "+f"(d[0]), "+f"(d[1]), "+f"(d[2]), "+f"(d[3])
        : "r"(a[0]), "r"(a[1]), "r"(a[2]), "r"(a[3]), "r"(b0), "r"(b1));
}

// Packed fp32 pair (FFMA2) helpers
typedef unsigned long long u64t;
__device__ __forceinline__ u64t pack2(float a, float b) {
    u64t r; asm("mov.b64 %0, {%1,%2};" : "=l"(r) : "f"(a), "f"(b)); return r;
}
__device__ __forceinline__ void unpack2(u64t v, float& a, float& b) {
    asm("mov.b64 {%0,%1}, %2;" : "=f"(a), "=f"(b) : "l"(v));
}
__device__ __forceinline__ u64t fma2(u64t a, u64t b, u64t c) {
    u64t d; asm("fma.rn.f32x2 %0, %1, %2, %3;" : "=l"(d) : "l"(a), "l"(b), "l"(c)); return d;
}

// Fast activations (errors ~1e-5, budget 1e-3)
__device__ __forceinline__ float tanha(float x) {
    float y; asm("tanh.approx.f32 %0, %1;" : "=f"(y) : "f"(x)); return y;
}
// sigmoid(x) = 0.5 + 0.5*tanh(x/2)
__device__ __forceinline__ float sigf(float x) {
    return fmaf(tanha(0.5f * x), 0.5f, 0.5f);
}

// ---------------- fused prep: whhT4, wl1T, pooled, conv_w, conv_bx (ONE launch) ----------------
__global__ void fused_prep(const float* __restrict__ wh0, const float* __restrict__ wh1,
                           const float* __restrict__ wh2, const float* __restrict__ wh3,
                           const float* __restrict__ wl1,
                           const float* __restrict__ wi0, const float* __restrict__ wi1,
                           const float* __restrict__ wi2, const float* __restrict__ wi3,
                           const float* __restrict__ bx,
                           float4* __restrict__ whhT4, float* __restrict__ wl1T,
                           float* __restrict__ pooled,
                           __nv_bfloat16* __restrict__ Wb,
                           __nv_bfloat16* __restrict__ Ahi, __nv_bfloat16* __restrict__ Alo) {
    size_t idx = (size_t)blockIdx.x * blockDim.x + threadIdx.x;
    if (idx < 4 * HH * HH) {
        int mat = (int)(idx >> 14), rem = (int)(idx & 16383);
        int k = rem >> 7, h = rem & 127;
        const float* w = (mat == 0) ? wh0 : (mat == 1) ? wh1 : (mat == 2) ? wh2 : wh3;
        whhT4[idx] = make_float4(w[(0   + h) * HH + k], w[(128 + h) * HH + k],
                                 w[(256 + h) * HH + k], w[(384 + h) * HH + k]);
    }
    if (idx < 456 * HH) {
        int f = (int)(idx >> 7), o = (int)(idx & 127);
        wl1T[idx] = wl1[o * 456 + f];
    }
    if (idx < BB * HH) pooled[idx] = -2.0f;
    if (idx < (size_t)4 * GG * KP) {
        int p = (int)(idx / (GG * KP)), rem = (int)(idx % (GG * KP));
        int n = rem >> 8, k = rem & 255;
        const float* w = (p == 0) ? wi0 : (p == 1) ? wi1 : (p == 2) ? wi2 : wi3;
        int K = (p < 2) ? DD : 2 * HH;
        float v = (k < K) ? w[(size_t)n * K + k] : 0.f;
        __nv_bfloat16 h = __float2bfloat16(v);
        Wb[(size_t)(2 * p) * GG * KP + rem] = h;
        Wb[(size_t)(2 * p + 1) * GG * KP + rem] = __float2bfloat16(v - __bfloat162float(h));
    }
    if (idx < (size_t)MM * KP) {
        int m = (int)(idx >> 8), k = (int)(idx & 255);
        int t = m >> 9, b = m & 511;
        float v = (k < DD) ? bx[(size_t)b * TN * DD + (size_t)t * DD + k] : 0.f;
        __nv_bfloat16 h = __float2bfloat16(v);
        Ahi[idx] = h;
        Alo[idx] = __float2bfloat16(v - __bfloat162float(h));
    }
}

// ---------------- HMMA projection GEMM ----------------
#define SROW 144
#define TILE_B (128 * SROW)
#define SMEM_PROJ (4 * TILE_B)
__global__ __launch_bounds__(256, 2) void proj_mma(
    const __nv_bfloat16* __restrict__ Ahi, const __nv_bfloat16* __restrict__ Alo,
    const __nv_bfloat16* __restrict__ Whi, const __nv_bfloat16* __restrict__ Wlo,
    const float* __restrict__ b1, const float* __restrict__ b2,
    float* __restrict__ C) {
    extern __shared__ __align__(16) unsigned char dsm[];
    __shared__ float bias[128];
    int tid = threadIdx.x, lane = tid & 31, wid = tid >> 5;
    int wm = wid & 3, wn = wid >> 2;
    int m0 = blockIdx.y * 128, n0 = blockIdx.x * 128;
    if (tid < 128) bias[tid] = b1[n0 + tid] + b2[n0 + tid];

    uint32_t sa0 = smem_u32(dsm);
    uint32_t sb0 = sa0 + 2 * TILE_B;
    const __nv_bfloat16* Asegs[3] = { Ahi, Ahi, Alo };
    const __nv_bfloat16* Wsegs[3] = { Whi, Wlo, Whi };
    const int total = 12;

    auto load_chunk = [&](int c, int buf) {
        int seg = c >> 2;
        int ko = (c & 3) * 64;
        const __nv_bfloat16* As = Asegs[seg] + (size_t)m0 * KP + ko;
        const __nv_bfloat16* Ws = Wsegs[seg] + (size_t)n0 * KP + ko;
#pragma unroll
        for (int i = 0; i < 4; i++) {
            int idx = tid + i * 256;
            int row = idx >> 3, w = idx & 7;
            CP_ASYNC16(sa0 + buf * TILE_B + row * SROW + w * 16,
                       As + (size_t)row * KP + w * 8);
            CP_ASYNC16(sb0 + buf * TILE_B + row * SROW + w * 16,
                       Ws + (size_t)row * KP + w * 8);
        }
        CP_COMMIT();
    };

    float acc[2][8][4] = {};
    load_chunk(0, 0);
    load_chunk(1, 1);

    for (int c = 0; c < total; c++) {
        int buf = c & 1;
        if (c + 1 < total) CP_WAIT1(); else CP_WAIT0();
        __syncthreads();
        uint32_t ab = sa0 + buf * TILE_B;
        uint32_t bb = sb0 + buf * TILE_B;
#pragma unroll
        for (int ks = 0; ks < 4; ks++) {
            uint32_t a[2][4], b[4][4];
#pragma unroll
            for (int mt = 0; mt < 2; mt++) {
                uint32_t addr = ab + (uint32_t)(wm * 32 + mt * 16 + (lane & 15)) * SROW
                                   + (uint32_t)(ks * 16 + ((lane & 16) ? 8 : 0)) * 2;
                ldsm_x4(a[mt][0], a[mt][1], a[mt][2], a[mt][3], addr);
            }
#pragma unroll
            for (int np = 0; np < 4; np++) {
                uint32_t addr = bb + (uint32_t)(wn * 64 + np * 16 + (lane & 7) + ((lane & 16) ? 8 : 0)) * SROW
                                   + (uint32_t)(ks * 16 + ((lane & 8) ? 8 : 0)) * 2;
                ldsm_x4(b[np][0], b[np][1], b[np][2], b[np][3], addr);
            }
#pragma unroll
            for (int mt = 0; mt < 2; mt++)
#pragma unroll
                for (int nt = 0; nt < 8; nt++)
                    mma16816(acc[mt][nt], a[mt], b[nt >> 1][(nt & 1) * 2],
                             b[nt >> 1][(nt & 1) * 2 + 1]);
        }
        __syncthreads();
        if (c + 2 < total) load_chunk(c + 2, buf);
    }

#pragma unroll
    for (int mt = 0; mt < 2; mt++)
#pragma unroll
        for (int nt = 0; nt < 8; nt++) {
            int row  = m0 + wm * 32 + mt * 16 + (lane >> 2);
            int colL = wn * 64 + nt * 8 + (lane & 3) * 2;
            int col  = n0 + colL;
            float2 v0 = { acc[mt][nt][0] + bias[colL], acc[mt][nt][1] + bias[colL + 1] };
            float2 v1 = { acc[mt][nt][2] + bias[colL], acc[mt][nt][3] + bias[colL + 1] };
            *(float2*)(C + (size_t)row * 512 + col) = v0;
            *(float2*)(C + (size_t)(row + 8) * 512 + col) = v1;
        }
}

// ---------------- fused bidirectional LSTM recurrence (gate-pair split) ----------------
// 256 threads = 128 hcol x 2 gate-pairs (gp). Thread (hcol, gp) accumulates its
// gate pair for ALL 8 batch rows -> every smem weight byte is read exactly once
// (crossbar volume/step halves vs row-split: 544 -> 320 B/warp/k).
// Weights k<KS in smem (u64 gate-pair, gp-major); k>=KS streamed as float2 LDGs.
// h stored k-major packed {h,h}, HPAD=10: rows broadcast as 4x LDS.128.
// Per-step accumulator exchange through an 8KB smem buffer restores the
// 4-rows-per-thread epilogue (r0 = gp*4). Approx activations; mode 1 writes the
// bf16 hi/lo split directly.
#define HPAD 10
#define KS 96
#define KT (128 - KS)   // 32 tail k-values
#define LSTM_WSM (KS * 2 * HH * sizeof(u64t))       // 196608
#define LSTM_HSM (2 * HH * HPAD * sizeof(u64t))     // 20480
#define LSTM_XCH (2 * HH * 4 * sizeof(u64t))        // 8192
#define LSTM_SMEM (LSTM_WSM + LSTM_HSM + LSTM_XCH)  // 225280
__global__ __launch_bounds__(256) void lstm_kernel(
    const float* __restrict__ xpF, const float* __restrict__ xpB,
    const float4* __restrict__ whhT4F, const float4* __restrict__ whhT4B,
    const float* __restrict__ hf,
    float* __restrict__ outF, float* __restrict__ outB, int outStride,
    __nv_bfloat16* __restrict__ ohi, __nv_bfloat16* __restrict__ olo, int mode) {
    extern __shared__ __align__(16) unsigned char lsm[];
    u64t* wsh2 = (u64t*)lsm;                               // [KS][2(gp)][HH]
    u64t* hshp = (u64t*)(lsm + LSTM_WSM);                  // [2][HH(k)][HPAD]
    u64t* xch  = (u64t*)(lsm + LSTM_WSM + LSTM_HSM);       // [2(gp)][HH][4]
    int dir = blockIdx.x & 1;
    int rb = (blockIdx.x >> 1) * 8;
    const float*  xp  = dir ? xpB    : xpF;
    const float4* wT4 = dir ? whhT4B : whhT4F;
    float*        out = dir ? outB   : outF;
    int tid = threadIdx.x;
    int hcol = tid & 127;
    int gp = tid >> 7;          // gate-pair: 0 -> (i,f), 1 -> (c,o)
    int r0 = gp * 4;            // epilogue rows

    // one-time: cache k<KS weights, pre-packed as u64 gate pairs (gp-major)
    for (int i = tid; i < KS * HH; i += 256) {
        int k = i >> 7, h = i & 127;
        float4 w4 = wT4[i];
        wsh2[k * 256 + h]       = pack2(w4.x, w4.y);
        wsh2[k * 256 + 128 + h] = pack2(w4.z, w4.w);
    }

    float hfv = hf[hcol];
    float c[4];
#pragma unroll
    for (int r = 0; r < 4; r++) c[r] = hfv;
    if (gp == 0) {
        u64t hp = pack2(hfv, hfv);
#pragma unroll
        for (int r = 0; r < 8; r++) hshp[(size_t)hcol * HPAD + r] = hp;
    }
    __syncthreads();

    const float2* wb2 = (const float2*)wT4;   // float4 -> 2x float2; gp selects half

    for (int t = 0; t < TN; t++) {
        int tef = dir ? (TN - 1 - t) : t;
        int cur = t & 1;
        const u64t* hcur = hshp + (size_t)cur * HH * HPAD;

        // xp loads for this thread's epilogue rows — hidden under the k-loop
        float xr[4][4];
        size_t rowbase = ((size_t)tef * BB + rb + r0) * GG + hcol;
#pragma unroll
        for (int r = 0; r < 4; r++) {
            const float* p = xp + rowbase + (size_t)r * GG;
            xr[r][0] = p[0];   xr[r][1] = p[128];
            xr[r][2] = p[256]; xr[r][3] = p[384];
        }

        // prefetch first global tail chunk (this thread's gate-pair slice)
        float2 wc[8];
#pragma unroll
        for (int j = 0; j < 8; j++)
            wc[j] = wb2[((size_t)(KS + j) * HH + hcol) * 2 + gp];

        u64t a[8] = {0ull,0ull,0ull,0ull,0ull,0ull,0ull,0ull};

        // ---- smem bulk: k in [0,KS) — 1 LDS.64 weight + 4 broadcast LDS.128 h ----
#pragma unroll 8
        for (int k = 0; k < KS; k++) {
            u64t w = wsh2[k * 256 + gp * 128 + hcol];
            const u64t* hp = hcur + k * HPAD;
            ulonglong2 h01 = *(const ulonglong2*)(hp);
            ulonglong2 h23 = *(const ulonglong2*)(hp + 2);
            ulonglong2 h45 = *(const ulonglong2*)(hp + 4);
            ulonglong2 h67 = *(const ulonglong2*)(hp + 6);
            a[0] = fma2(h01.x, w, a[0]); a[1] = fma2(h01.y, w, a[1]);
            a[2] = fma2(h23.x, w, a[2]); a[3] = fma2(h23.y, w, a[3]);
            a[4] = fma2(h45.x, w, a[4]); a[5] = fma2(h45.y, w, a[5]);
            a[6] = fma2(h67.x, w, a[6]); a[7] = fma2(h67.y, w, a[7]);
        }

        // ---- global tail: k in [KS,128), rolling depth-8 prefetch ----
#pragma unroll
        for (int kc = 0; kc < KT; kc += 8) {
            float2 wn[8];
            if (kc + 8 < KT) {
#pragma unroll
                for (int j = 0; j < 8; j++)
                    wn[j] = wb2[((size_t)(KS + kc + 8 + j) * HH + hcol) * 2 + gp];
            }
#pragma unroll
            for (int j = 0; j < 8; j++) {
                int k = KS + kc + j;
                u64t w = pack2(wc[j].x, wc[j].y);
                const u64t* hp = hcur + k * HPAD;
                ulonglong2 h01 = *(const ulonglong2*)(hp);
                ulonglong2 h23 = *(const ulonglong2*)(hp + 2);
                ulonglong2 h45 = *(const ulonglong2*)(hp + 4);
                ulonglong2 h67 = *(const ulonglong2*)(hp + 6);
                a[0] = fma2(h01.x, w, a[0]); a[1] = fma2(h01.y, w, a[1]);
                a[2] = fma2(h23.x, w, a[2]); a[3] = fma2(h23.y, w, a[3]);
                a[4] = fma2(h45.x, w, a[4]); a[5] = fma2(h45.y, w, a[5]);
                a[6] = fma2(h67.x, w, a[6]); a[7] = fma2(h67.y, w, a[7]);
            }
            if (kc + 8 < KT) {
#pragma unroll
                for (int j = 0; j < 8; j++) wc[j] = wn[j];
            }
        }

        // ---- exchange: give partner the 4 rows it epilogues ----
        // gp0 epilogues rows 0-3 (has a01 all rows, needs a23 rows 0-3 from gp1)
        // gp1 epilogues rows 4-7 (has a23 all rows, needs a01 rows 4-7 from gp0)
        u64t* xme = xch + ((size_t)gp * HH + hcol) * 4;
        {
            ulonglong2 s0, s1;
            if (gp == 0) { s0.x = a[4]; s0.y = a[5]; s1.x = a[6]; s1.y = a[7]; }
            else         { s0.x = a[0]; s0.y = a[1]; s1.x = a[2]; s1.y = a[3]; }
            *(ulonglong2*)xme = s0;
            *(ulonglong2*)(xme + 2) = s1;
        }
        __syncthreads();
        u64t p4[4];
        {
            const u64t* xpr = xch + ((size_t)(1 - gp) * HH + hcol) * 4;
            ulonglong2 l0 = *(const ulonglong2*)xpr;
            ulonglong2 l1 = *(const ulonglong2*)(xpr + 2);
            p4[0] = l0.x; p4[1] = l0.y; p4[2] = l1.x; p4[3] = l1.y;
        }

        // ---- epilogue: rows r0..r0+3 ----
        u64t* hw = hshp + ((size_t)(cur ^ 1) * HH + hcol) * HPAD + r0;
        u64t hnew[4];
#pragma unroll
        for (int r = 0; r < 4; r++) {
            u64t v01 = (gp == 0) ? a[r]  : p4[r];
            u64t v23 = (gp == 0) ? p4[r] : a[4 + r];
            float gi, gf_, gc, go;
            unpack2(v01, gi, gf_);
            unpack2(v23, gc, go);
            gi  += xr[r][0]; gf_ += xr[r][1];
            gc  += xr[r][2]; go  += xr[r][3];
            float ig = sigf(gi), fg = sigf(gf_);
            float cc = tanha(gc), og = sigf(go);
            float cv = fg * c[r] + ig * cc;
            c[r] = cv;
            float hv = og * tanha(cv);
            hnew[r] = pack2(hv, hv);
            size_t row = (size_t)tef * BB + rb + r0 + r;
            if (mode == 0) {
                out[row * outStride + hcol] = hv;
            } else {
                size_t o = row * KP + dir * 128 + hcol;
                __nv_bfloat16 hh = __float2bfloat16(hv);
                ohi[o] = hh;
                olo[o] = __float2bfloat16(hv - __bfloat162float(hh));
            }
        }
        ulonglong2 s0; s0.x = hnew[0]; s0.y = hnew[1];
        ulonglong2 s1; s1.x = hnew[2]; s1.y = hnew[3];
        *(ulonglong2*)hw = s0;
        *(ulonglong2*)(hw + 2) = s1;
        __syncthreads();
    }
}

// ---------------- classifier: h = tanh(data @ w_l1^T), max over t ----------------
#define CTT 16
__global__ __launch_bounds__(256) void cls_kernel(
    const float* __restrict__ f1, const float* __restrict__ r1,
    const float* __restrict__ bx, const float* __restrict__ hf,
    const float* __restrict__ wl1T, float* __restrict__ pooled) {
    __shared__ float ds[CTT][456];
    int b = blockIdx.x;
    int tile = blockIdx.y;
    int tid = threadIdx.x;
    for (int idx = tid; idx < CTT * 456; idx += 256) {
        int tt = idx / 456, f = idx % 456;
        int t = tile * CTT + tt;
        float v = 0.f;
        if (t < TN) {
            if (f < 128) {
                v = (t == 0) ? hf[f] : f1[((size_t)t * BB + b) * HH + f];
            } else if (f < 328) {
                v = bx[(size_t)b * TN * DD + (size_t)t * DD + (f - 128)];
            } else {
                int j = f - 328;
                v = (t == TN - 1) ? hf[j] : r1[((size_t)(TN - 2 - t) * BB + b) * HH + j];
            }
        }
        ds[tt][f] = v;
    }
    __syncthreads();

    int o2 = (tid & 63) * 2;
    int tsub = tid >> 6;
    float acc[4][2];
#pragma unroll
    for (int q = 0; q < 4; q++) { acc[q][0] = 0.f; acc[q][1] = 0.f; }
    for (int f = 0; f < 456; f++) {
        float2 w = *(const float2*)(wl1T + f * HH + o2);
#pragma unroll
        for (int q = 0; q < 4; q++) {
            float dv = ds[tsub + q * 4][f];
            acc[q][0] += dv * w.x;
            acc[q][1] += dv * w.y;
        }
    }
    float m0v = -2.f, m1v = -2.f;
#pragma unroll
    for (int q = 0; q < 4; q++) {
        int t = tile * CTT + tsub + q * 4;
        if (t < TN) {
            m0v = fmaxf(m0v, tanha(acc[q][0]));
            m1v = fmaxf(m1v, tanha(acc[q][1]));
        }
    }
    atomicMaxF(&pooled[b * HH + o2],     m0v);
    atomicMaxF(&pooled[b * HH + o2 + 1], m1v);
}

// ---------------- final head ----------------
__global__ void out_kernel(const float* __restrict__ pooled,
                           const float* __restrict__ wl2, const float* __restrict__ bl2,
                           const int* __restrict__ by, float* __restrict__ outb,
                           int out_size) {
    __shared__ float sh[128];
    int b = blockIdx.x, tid = threadIdx.x;
    float p = pooled[b * 128 + tid];
    for (int o = 0; o < 4; o++) {
        float v = p * wl2[o * 128 + tid];
        sh[tid] = v;
        __syncthreads();
        if (tid < 64) sh[tid] += sh[tid + 64];
        __syncthreads();
        if (tid < 32) {
            float s = sh[tid] + sh[tid + 32];
            for (int off = 16; off; off >>= 1) s += __shfl_down_sync(0xffffffffu, s, off);
            if (tid == 0) outb[b * 4 + o] = s + bl2[o];
        }
        __syncthreads();
    }
    if (tid == 0 && out_size >= BB * 4 + BB) outb[BB * 4 + b] = (float)by[b];
}

// ---------------- launch ----------------
extern "C" void kernel_launch(void* const* d_in, const int* in_sizes, int n_in,
                              void* d_out, int out_size) {
    const float* bx       = (const float*)d_in[0];
    const int*   by       = (const int*)  d_in[1];
    const float* hf       = (const float*)d_in[2];
    const float* w_ih[4]  = { (const float*)d_in[3],  (const float*)d_in[7],
                              (const float*)d_in[11], (const float*)d_in[15] };
    const float* w_hh[4]  = { (const float*)d_in[4],  (const float*)d_in[8],
                              (const float*)d_in[12], (const float*)d_in[16] };
    const float* b_ih[4]  = { (const float*)d_in[5],  (const float*)d_in[9],
                              (const float*)d_in[13], (const float*)d_in[17] };
    const float* b_hh[4]  = { (const float*)d_in[6],  (const float*)d_in[10],
                              (const float*)d_in[14], (const float*)d_in[18] };
    const float* wl1      = (const float*)d_in[19];
    const float* wl2      = (const float*)d_in[20];
    const float* bl2      = (const float*)d_in[21];
    float* outb = (float*)d_out;

    float *xpA, *xpB, *f1, *r1, *wl1T, *pooled;
    float4* whhT4;
    __nv_bfloat16 *Ahi, *Alo, *Wb;
    cudaGetSymbolAddress((void**)&xpA,    g_xpA);
    cudaGetSymbolAddress((void**)&xpB,    g_xpB);
    cudaGetSymbolAddress((void**)&f1,     g_f1);
    cudaGetSymbolAddress((void**)&r1,     g_r1);
    cudaGetSymbolAddress((void**)&whhT4,  g_whhT4);
    cudaGetSymbolAddress((void**)&wl1T,   g_wl1T);
    cudaGetSymbolAddress((void**)&pooled, g_pooled);
    cudaGetSymbolAddress((void**)&Ahi,    g_Ahi);
    cudaGetSymbolAddress((void**)&Alo,    g_Alo);
    cudaGetSymbolAddress((void**)&Wb,     g_W);

    cudaFuncSetAttribute(proj_mma, cudaFuncAttributeMaxDynamicSharedMemorySize, SMEM_PROJ);
    cudaFuncSetAttribute(lstm_kernel, cudaFuncAttributeMaxDynamicSharedMemorySize, LSTM_SMEM);

    dim3 pg(GG / 128, MM / 128);  // (4, 1200)

    // 0: all prep/conversions in ONE launch
    fused_prep<<<(int)(((size_t)MM * KP + 255) / 256), 256>>>(
        w_hh[0], w_hh[1], w_hh[2], w_hh[3], wl1,
        w_ih[0], w_ih[1], w_ih[2], w_ih[3], bx,
        whhT4, wl1T, pooled, Wb, Ahi, Alo);

    // 1,2: layer-0 projections
    proj_mma<<<pg, 256, SMEM_PROJ>>>(Ahi, Alo, Wb, Wb + (size_t)GG * KP,
                                     b_ih[0], b_hh[0], xpA);
    proj_mma<<<pg, 256, SMEM_PROJ>>>(Ahi, Alo, Wb + (size_t)2 * GG * KP, Wb + (size_t)3 * GG * KP,
                                     b_ih[1], b_hh[1], xpB);
    // 3: layer-0 recurrence (ncu sample slot = launch idx 3)
    //    writes bf16 hi/lo split directly into Ahi/Alo (mode 1)
    lstm_kernel<<<128, 256, LSTM_SMEM>>>(xpA, xpB, whhT4, whhT4 + HH * HH, hf,
                                         nullptr, nullptr, 0, Ahi, Alo, 1);

    // 4,5: layer-1 projections
    proj_mma<<<pg, 256, SMEM_PROJ>>>(Ahi, Alo, Wb + (size_t)4 * GG * KP, Wb + (size_t)5 * GG * KP,
                                     b_ih[2], b_hh[2], xpA);
    proj_mma<<<pg, 256, SMEM_PROJ>>>(Ahi, Alo, Wb + (size_t)6 * GG * KP, Wb + (size_t)7 * GG * KP,
                                     b_ih[3], b_hh[3], xpB);
    // 6: layer-1 recurrence -> f1, r1 (mode 0)
    lstm_kernel<<<128, 256, LSTM_SMEM>>>(xpA, xpB, whhT4 + 2 * HH * HH, whhT4 + 3 * HH * HH, hf,
                                         f1, r1, HH, nullptr, nullptr, 0);

    // 7: classifier + maxpool
    dim3 cg(BB, (TN + CTT - 1) / CTT);
    cls_kernel<<<cg, 256>>>(f1, r1, bx, hf, wl1T, pooled);
    // 8: head + b_y passthrough
    out_kernel<<<BB, 128>>>(pooled, wl2, bl2, by, outb, out_size);
}